// round 13
// baseline (speedup 1.0000x reference)
#include <cuda_runtime.h>
#include <cuda_bf16.h>
#include <cstdint>

#define N_NODES 50000
#define N_EDGES 300000
#define MAXF    256

// ---------------- scratch (device globals; no allocation allowed) ----------
__device__ float g_support[(size_t)N_NODES * MAXF];
__device__ float g_l3     [(size_t)N_NODES * MAXF];
__device__ float g_l4     [(size_t)N_NODES * MAXF];   // also l1/l2 temp
// bf16 hi/lo planes (two sets to avoid in-kernel read/write races)
__device__ unsigned short g_ahi[(size_t)N_NODES * MAXF];
__device__ unsigned short g_alo[(size_t)N_NODES * MAXF];
__device__ unsigned short g_bhi[(size_t)N_NODES * MAXF];
__device__ unsigned short g_blo[(size_t)N_NODES * MAXF];
// bf16 hi/lo planes for weights, flat-packed per layer
#define W_TOTAL 245760
__device__ unsigned short g_whi[W_TOTAL];
__device__ unsigned short g_wlo[W_TOTAL];
// CSR-by-dst edge grouping (rebuilt every call)
__device__ int    g_counts[N_NODES];
__device__ int    g_start [N_NODES];
__device__ int    g_wp    [N_NODES];
__device__ int    g_cursor;
__device__ float2 g_ebuf  [N_EDGES];    // (src as int bits, weight)

// =================== small helpers =========================================
__device__ __forceinline__ uint32_t smem_u32(const void* p) {
    uint32_t a;
    asm("{ .reg .u64 t; cvta.to.shared.u64 t, %1; cvt.u32.u64 %0, t; }"
        : "=r"(a) : "l"(p));
    return a;
}
__device__ __forceinline__ unsigned short f2bf(float x) {
    __nv_bfloat16 b = __float2bfloat16(x);
    return *(unsigned short*)&b;
}
__device__ __forceinline__ float bf2f(unsigned short u) {
    __nv_bfloat16 b = *(__nv_bfloat16*)&u;
    return __bfloat162float(b);
}
__device__ __forceinline__ void cp16(uint32_t dst, const void* src, bool valid) {
    int sz = valid ? 16 : 0;
    asm volatile("cp.async.cg.shared.global [%0], [%1], 16, %2;"
                 :: "r"(dst), "l"(src), "r"(sz));
}
__device__ __forceinline__ void ldsm4(uint32_t* r, uint32_t addr) {
    asm volatile("ldmatrix.sync.aligned.m8n8.x4.shared.b16 {%0,%1,%2,%3}, [%4];"
                 : "=r"(r[0]), "=r"(r[1]), "=r"(r[2]), "=r"(r[3]) : "r"(addr));
}
__device__ __forceinline__ void ldsm4t(uint32_t* r, uint32_t addr) {
    asm volatile("ldmatrix.sync.aligned.m8n8.x4.trans.shared.b16 {%0,%1,%2,%3}, [%4];"
                 : "=r"(r[0]), "=r"(r[1]), "=r"(r[2]), "=r"(r[3]) : "r"(addr));
}
__device__ __forceinline__ void mma_bf16(float* d, const uint32_t* a,
                                         uint32_t b0, uint32_t b1) {
    asm volatile(
        "mma.sync.aligned.m16n8k16.row.col.f32.bf16.bf16.f32 "
        "{%0,%1,%2,%3}, {%4,%5,%6,%7}, {%8,%9}, {%0,%1,%2,%3};"
        : "+f"(d[0]), "+f"(d[1]), "+f"(d[2]), "+f"(d[3])
        : "r"(a[0]), "r"(a[1]), "r"(a[2]), "r"(a[3]), "r"(b0), "r"(b1));
}

// ========== bf16x3 mma.sync GEMM: C[M,N] = A[M,K] @ W[K,N] =================
// 3-stage cp.async pipeline, ONE __syncthreads per K-tile.
// Optional fused epilogue: bias+relu (if bias) ; fp32 out (if C) ;
// bf16 hi/lo plane out (if hi).
template<int K, int BN>
__global__ __launch_bounds__(256, 1) void gemm_bf16x3_kernel(
    const unsigned short* __restrict__ Ahi, const unsigned short* __restrict__ Alo,
    const unsigned short* __restrict__ Whi, const unsigned short* __restrict__ Wlo,
    float* __restrict__ C, int M, int N,
    const float* __restrict__ bias,
    unsigned short* __restrict__ hi, unsigned short* __restrict__ lo)
{
    constexpr int NT   = K / 32;
    constexpr int BB   = 64 * BN;
    constexpr int BUFB = 16384 + 2 * BB;
    constexpr int NTN  = BN / 16;
    constexpr int NP   = NTN / 2;
    constexpr int BC   = BN / 8;

    extern __shared__ __align__(128) char smem[];
    const uint32_t sb = smem_u32(smem);

    const int tid  = threadIdx.x;
    const int lane = tid & 31;
    const int wid  = tid >> 5;
    const int m0   = blockIdx.x * 128;
    const int bn0  = blockIdx.y * BN;
    const int wm   = (wid & 3) * 32;
    const int wn   = (wid >> 2) * (BN / 2);

    float acc[2][NTN][4];
    #pragma unroll
    for (int i = 0; i < 2; i++)
        #pragma unroll
        for (int j = 0; j < NTN; j++)
            #pragma unroll
            for (int k = 0; k < 4; k++) acc[i][j][k] = 0.f;

    auto load_tile = [&](int t, int b) {
        const uint32_t base = sb + b * BUFB;
        const int kr0 = t * 32;
        #pragma unroll
        for (int i = tid; i < 512; i += 256) {
            int r = i >> 2, c = i & 3;
            int gr = m0 + r;
            uint32_t d = base + r * 64 + ((c ^ ((r >> 1) & 3)) << 4);
            size_t go = (size_t)gr * K + kr0 + c * 8;
            cp16(d,        Ahi + go, gr < M);
            cp16(d + 8192, Alo + go, gr < M);
        }
        #pragma unroll
        for (int i = tid; i < 32 * BC; i += 256) {
            int r = i / BC, c = i % BC;
            uint32_t d = base + 16384 + r * (BN * 2) + ((c ^ (r & 7)) << 4);
            size_t go = (size_t)(kr0 + r) * N + bn0 + c * 8;
            cp16(d,      Whi + go, true);
            cp16(d + BB, Wlo + go, true);
        }
        asm volatile("cp.async.commit_group;" ::: "memory");
    };

    auto compute = [&](int b) {
        const uint32_t base  = sb + b * BUFB;
        const uint32_t baseB = base + 16384;
        #pragma unroll
        for (int ks = 0; ks < 2; ks++) {
            uint32_t ah[2][4], al[2][4];
            int lrow = lane & 15;
            int lch  = 2 * ks + (lane >> 4);
            #pragma unroll
            for (int mt = 0; mt < 2; mt++) {
                int r = wm + mt * 16 + lrow;
                uint32_t addr = base + r * 64 + ((lch ^ ((r >> 1) & 3)) << 4);
                ldsm4(ah[mt], addr);
                ldsm4(al[mt], addr + 8192);
            }
            uint32_t bh[NP][4], bl[NP][4];
            int kr = ks * 16 + (lane & 15);
            #pragma unroll
            for (int np = 0; np < NP; np++) {
                int cb = (wn + np * 16 + (lane >> 4) * 8) >> 3;
                uint32_t addr = baseB + kr * (BN * 2) + ((cb ^ (kr & 7)) << 4);
                ldsm4t(bh[np], addr);
                ldsm4t(bl[np], addr + BB);
            }
            #pragma unroll
            for (int mt = 0; mt < 2; mt++)
                #pragma unroll
                for (int np = 0; np < NP; np++) {
                    mma_bf16(acc[mt][2*np],   ah[mt], bh[np][0], bh[np][1]);
                    mma_bf16(acc[mt][2*np],   ah[mt], bl[np][0], bl[np][1]);
                    mma_bf16(acc[mt][2*np],   al[mt], bh[np][0], bh[np][1]);
                    mma_bf16(acc[mt][2*np+1], ah[mt], bh[np][2], bh[np][3]);
                    mma_bf16(acc[mt][2*np+1], ah[mt], bl[np][2], bl[np][3]);
                    mma_bf16(acc[mt][2*np+1], al[mt], bh[np][2], bh[np][3]);
                }
        }
    };

    // 3-stage pipeline prologue
    load_tile(0, 0);
    if (NT > 1) load_tile(1, 1);

    #pragma unroll 1
    for (int t = 0; t < NT; t++) {
        if (t + 1 < NT) {
            asm volatile("cp.async.wait_group 1;" ::: "memory");
        } else {
            asm volatile("cp.async.wait_group 0;" ::: "memory");
        }
        __syncthreads();
        compute(t % 3);
        if (t + 2 < NT) load_tile(t + 2, (t + 2) % 3);
    }

    // fused epilogue
    #pragma unroll
    for (int mt = 0; mt < 2; mt++)
        #pragma unroll
        for (int nt = 0; nt < NTN; nt++) {
            int row = m0 + wm + mt * 16 + (lane >> 2);
            int col = bn0 + wn + nt * 8 + (lane & 3) * 2;
            float v0 = acc[mt][nt][0], v1 = acc[mt][nt][1];
            float v2 = acc[mt][nt][2], v3 = acc[mt][nt][3];
            if (bias) {
                float b0 = __ldg(&bias[col]);
                float b1 = __ldg(&bias[col + 1]);
                v0 = fmaxf(v0 + b0, 0.f); v1 = fmaxf(v1 + b1, 0.f);
                v2 = fmaxf(v2 + b0, 0.f); v3 = fmaxf(v3 + b1, 0.f);
            }
            if (row < M) {
                size_t o = (size_t)row * N + col;
                if (C) *(float2*)&C[o] = make_float2(v0, v1);
                if (hi) {
                    ushort2 h2, l2;
                    h2.x = f2bf(v0); l2.x = f2bf(v0 - bf2f(h2.x));
                    h2.y = f2bf(v1); l2.y = f2bf(v1 - bf2f(h2.y));
                    *(ushort2*)&hi[o] = h2;
                    *(ushort2*)&lo[o] = l2;
                }
            }
            if (row + 8 < M) {
                size_t o = (size_t)(row + 8) * N + col;
                if (C) *(float2*)&C[o] = make_float2(v2, v3);
                if (hi) {
                    ushort2 h2, l2;
                    h2.x = f2bf(v2); l2.x = f2bf(v2 - bf2f(h2.x));
                    h2.y = f2bf(v3); l2.y = f2bf(v3 - bf2f(h2.y));
                    *(ushort2*)&hi[o] = h2;
                    *(ushort2*)&lo[o] = l2;
                }
            }
        }
}

// ---------------- batched split: weights (6 segs) + x in ONE launch --------
struct SplitArgs {
    const float4* w[6];     // weight tensors
    const float4* x;        // input features
};
#define WSEG_BLOCKS 240     // 61440 float4s of weights / 256
#define XSEG_N4     1600000 // 50000*128/4

__global__ void split_all_kernel(SplitArgs a,
                                 ushort4* __restrict__ whi4, ushort4* __restrict__ wlo4,
                                 ushort4* __restrict__ ahi4, ushort4* __restrict__ alo4)
{
    int bid = blockIdx.x;
    float4 v;
    ushort4* dh;
    ushort4* dl;
    int oi;
    if (bid < WSEG_BLOCKS) {
        int i = bid * 256 + threadIdx.x;          // [0, 61440)
        int seg = (i >= 2048) + (i >= 4096) + (i >= 12288) + (i >= 28672) + (i >= 45056);
        static const int off[6] = {0, 2048, 4096, 12288, 28672, 45056};
        v = __ldg(&a.w[seg][i - off[seg]]);
        dh = whi4; dl = wlo4; oi = i;
    } else {
        int i = (bid - WSEG_BLOCKS) * 256 + threadIdx.x;
        if (i >= XSEG_N4) return;
        v = __ldg(&a.x[i]);
        dh = ahi4; dl = alo4; oi = i;
    }
    ushort4 h, l;
    h.x = f2bf(v.x); l.x = f2bf(v.x - bf2f(h.x));
    h.y = f2bf(v.y); l.y = f2bf(v.y - bf2f(h.y));
    h.z = f2bf(v.z); l.z = f2bf(v.z - bf2f(h.z));
    h.w = f2bf(v.w); l.w = f2bf(v.w - bf2f(h.w));
    dh[oi] = h; dl[oi] = l;
}

// ---------------- CSR build (4 tiny kernels) -------------------------------
__global__ void csr_zero_kernel()
{
    int i = blockIdx.x * blockDim.x + threadIdx.x;
    if (i < N_NODES) g_counts[i] = 0;
    if (i == 0) g_cursor = 0;
}
__global__ void csr_hist_kernel(const int* __restrict__ dst)
{
    int e = blockIdx.x * blockDim.x + threadIdx.x;
    if (e < N_EDGES) atomicAdd(&g_counts[dst[e]], 1);
}
__global__ void csr_alloc_kernel()
{
    int i = blockIdx.x * blockDim.x + threadIdx.x;
    if (i < N_NODES) {
        int s = atomicAdd(&g_cursor, g_counts[i]);
        g_start[i] = s;
        g_wp[i]    = s;
    }
}
__global__ void csr_scatter_kernel(const int* __restrict__ src,
                                   const int* __restrict__ dst,
                                   const float* __restrict__ w)
{
    int e = blockIdx.x * blockDim.x + threadIdx.x;
    if (e >= N_EDGES) return;
    int pos = atomicAdd(&g_wp[dst[e]], 1);
    g_ebuf[pos] = make_float2(__int_as_float(src[e]), w[e]);
}

// ====== fused aggregation: warp per node, 2-edge MLP =======================
// r = sum_e w_e * src_rows[src_e]; if bias: r = relu(r + bias)  (post mode)
//                                  else:    r = raw sum          (pre mode)
// optional: out_f32 <- r ; planes <- split(r + add1 + add2)
template<int N>
__global__ __launch_bounds__(256) void agg_fused_kernel(
    const float* __restrict__ src_rows,
    const float* __restrict__ bias,
    float* __restrict__ out_f32,
    ushort* __restrict__ hi, ushort* __restrict__ lo,
    const float* __restrict__ add1,
    const float* __restrict__ add2)
{
    int warp = (blockIdx.x * blockDim.x + threadIdx.x) >> 5;
    if (warp >= N_NODES) return;
    int lane = threadIdx.x & 31;
    int s   = __ldg(&g_start[warp]);
    int end = s + __ldg(&g_counts[warp]);

    constexpr int FPN = N / 32;    // 2, 4, or 8 floats per lane
    float acc[FPN];
    #pragma unroll
    for (int j = 0; j < FPN; j++) acc[j] = 0.f;

    auto gather1 = [&](float2 p) {
        int   src = __float_as_int(p.x);
        float w   = p.y;
        const float* row = src_rows + (size_t)src * N;
        if (FPN == 2) {
            float2 v = __ldg((const float2*)&row[lane * 2]);
            acc[0] += v.x * w; acc[1] += v.y * w;
        } else if (FPN == 4) {
            float4 v = __ldg((const float4*)&row[lane * 4]);
            acc[0] += v.x * w; acc[1] += v.y * w;
            acc[2] += v.z * w; acc[3] += v.w * w;
        } else {
            float4 v0 = __ldg((const float4*)&row[lane * 4]);
            float4 v1 = __ldg((const float4*)&row[128 + lane * 4]);
            acc[0] += v0.x * w; acc[1] += v0.y * w;
            acc[2] += v0.z * w; acc[3] += v0.w * w;
            acc[4] += v1.x * w; acc[5] += v1.y * w;
            acc[6] += v1.z * w; acc[7] += v1.w * w;
        }
    };

    int e = s;
    #pragma unroll 1
    for (; e + 1 < end; e += 2) {
        // both edge records first, then two independent row gathers -> MLP 2
        float2 p0 = __ldg(&g_ebuf[e]);
        float2 p1 = __ldg(&g_ebuf[e + 1]);
        gather1(p0);
        gather1(p1);
    }
    if (e < end) gather1(__ldg(&g_ebuf[e]));

    int col0 = (FPN == 2) ? lane * 2 : lane * 4;
    size_t rowo = (size_t)warp * N;

    float r[FPN];
    #pragma unroll
    for (int j = 0; j < FPN; j++) {
        int col = (j < 4) ? col0 + j : 128 + col0 + (j - 4);
        r[j] = bias ? fmaxf(acc[j] + __ldg(&bias[col]), 0.f) : acc[j];
    }
    if (out_f32) {
        if (FPN == 2)
            *(float2*)&out_f32[rowo + col0] = make_float2(r[0], r[1]);
        else {
            *(float4*)&out_f32[rowo + col0] = make_float4(r[0], r[1], r[2], r[3]);
            if (FPN == 8)
                *(float4*)&out_f32[rowo + 128 + col0] = make_float4(r[4], r[5], r[6], r[7]);
        }
    }
    if (hi) {
        float sv[FPN];
        #pragma unroll
        for (int j = 0; j < FPN; j++) sv[j] = r[j];
        if (add1) {
            #pragma unroll
            for (int j = 0; j < FPN; j++) {
                int col = (j < 4) ? col0 + j : 128 + col0 + (j - 4);
                sv[j] += __ldg(&add1[rowo + col]);
            }
        }
        if (add2) {
            #pragma unroll
            for (int j = 0; j < FPN; j++) {
                int col = (j < 4) ? col0 + j : 128 + col0 + (j - 4);
                sv[j] += __ldg(&add2[rowo + col]);
            }
        }
        unsigned short hv[FPN], lv[FPN];
        #pragma unroll
        for (int j = 0; j < FPN; j++) {
            hv[j] = f2bf(sv[j]);
            lv[j] = f2bf(sv[j] - bf2f(hv[j]));
        }
        if (FPN == 2) {
            *(ushort2*)&hi[rowo + col0] = make_ushort2(hv[0], hv[1]);
            *(ushort2*)&lo[rowo + col0] = make_ushort2(lv[0], lv[1]);
        } else {
            *(ushort4*)&hi[rowo + col0] = make_ushort4(hv[0], hv[1], hv[2], hv[3]);
            *(ushort4*)&lo[rowo + col0] = make_ushort4(lv[0], lv[1], lv[2], lv[3]);
            if (FPN == 8) {
                *(ushort4*)&hi[rowo + 128 + col0] = make_ushort4(hv[4], hv[5], hv[6], hv[7]);
                *(ushort4*)&lo[rowo + 128 + col0] = make_ushort4(lv[4], lv[5], lv[6], lv[7]);
            }
        }
    }
}

// ---------------------------------------------------------------------------
extern "C" void kernel_launch(void* const* d_in, const int* in_sizes, int n_in,
                              void* d_out, int out_size)
{
    const float* x    = (const float*)d_in[0];
    const int*   esrc = (const int*)  d_in[1];
    const int*   edst = (const int*)  d_in[2];
    const float* ew   = (const float*)d_in[3];
    const float* W[6];
    const float* b[6];
    for (int i = 0; i < 6; i++) {
        W[i] = (const float*)d_in[4 + 2 * i];
        b[i] = (const float*)d_in[5 + 2 * i];
    }

    float *support, *l3, *l4;
    unsigned short *ahi, *alo, *bhi, *blo, *whi, *wlo;
    cudaGetSymbolAddress((void**)&support, g_support);
    cudaGetSymbolAddress((void**)&l3,      g_l3);
    cudaGetSymbolAddress((void**)&l4,      g_l4);
    cudaGetSymbolAddress((void**)&ahi,     g_ahi);
    cudaGetSymbolAddress((void**)&alo,     g_alo);
    cudaGetSymbolAddress((void**)&bhi,     g_bhi);
    cudaGetSymbolAddress((void**)&blo,     g_blo);
    cudaGetSymbolAddress((void**)&whi,     g_whi);
    cudaGetSymbolAddress((void**)&wlo,     g_wlo);

    static const int woff[6] = {0, 8192, 16384, 49152, 114688, 180224};

    // 3-stage pipeline smem: BUFB*3; BN=64: 24576*3, BN=128: 32768*3
    cudaFuncSetAttribute(gemm_bf16x3_kernel<128, 64>,
        cudaFuncAttributeMaxDynamicSharedMemorySize, 73728);
    cudaFuncSetAttribute(gemm_bf16x3_kernel<64, 128>,
        cudaFuncAttributeMaxDynamicSharedMemorySize, 98304);
    cudaFuncSetAttribute(gemm_bf16x3_kernel<128, 128>,
        cudaFuncAttributeMaxDynamicSharedMemorySize, 98304);
    cudaFuncSetAttribute(gemm_bf16x3_kernel<256, 128>,
        cudaFuncAttributeMaxDynamicSharedMemorySize, 98304);

    // ---- CSR-by-dst build first ------------------------------------------
    csr_zero_kernel<<<(N_NODES + 255) / 256, 256>>>();
    csr_hist_kernel<<<(N_EDGES + 255) / 256, 256>>>(edst);
    csr_alloc_kernel<<<(N_NODES + 255) / 256, 256>>>();
    csr_scatter_kernel<<<(N_EDGES + 255) / 256, 256>>>(esrc, edst, ew);

    // ---- all splits in one launch ----------------------------------------
    {
        SplitArgs a;
        for (int i = 0; i < 6; i++) a.w[i] = (const float4*)W[i];
        a.x = (const float4*)x;
        int grid = WSEG_BLOCKS + (XSEG_N4 + 255) / 256;
        split_all_kernel<<<grid, 256>>>(a, (ushort4*)whi, (ushort4*)wlo,
                                        (ushort4*)ahi, (ushort4*)alo);
    }

    const int GRID_M   = (N_NODES + 127) / 128;            // 391
    const int AGG_GRID = (N_NODES * 32 + 255) / 256;       // warp per node

    // ---- L1 (agg-after): support = x@W1 ; l1 = relu(agg + b1) -> l4buf ----
    gemm_bf16x3_kernel<128, 64><<<dim3(GRID_M, 1), 256, 73728>>>(
        ahi, alo, whi + woff[0], wlo + woff[0], support, N_NODES, 64,
        nullptr, nullptr, nullptr);
    agg_fused_kernel<64><<<AGG_GRID, 256>>>(
        support, b[0], l4, nullptr, nullptr, nullptr, nullptr);    // l1 fp32

    // ---- L2 (agg-FIRST): planes = split(agg(l1)) ; l2 = relu(aggh@W2+b2) --
    agg_fused_kernel<64><<<AGG_GRID, 256>>>(
        l4, nullptr, nullptr, ahi, alo, nullptr, nullptr);         // pre-agg
    gemm_bf16x3_kernel<64, 128><<<dim3(GRID_M, 1), 256, 98304>>>(
        ahi, alo, whi + woff[1], wlo + woff[1], l4, N_NODES, 128,
        b[1], nullptr, nullptr);                                   // l2 fp32

    // ---- L3 (agg-FIRST): planes = split(agg(l2)) ;
    //      l3 = relu(aggh@W3+b3) -> g_l3 fp32 + planes(bhi/blo) ------------
    agg_fused_kernel<128><<<AGG_GRID, 256>>>(
        l4, nullptr, nullptr, ahi, alo, nullptr, nullptr);         // pre-agg
    gemm_bf16x3_kernel<128, 128><<<dim3(GRID_M, 2), 256, 98304>>>(
        ahi, alo, whi + woff[2], wlo + woff[2], l3, N_NODES, 256,
        b[2], bhi, blo);                                           // l3 + planes

    // ---- L4 (agg-after): support = l3@W4 ; l4 = relu(agg+b4) ;
    //      planes = split(l4+l3) -----------------------------------------
    gemm_bf16x3_kernel<256, 128><<<dim3(GRID_M, 2), 256, 98304>>>(
        bhi, blo, whi + woff[3], wlo + woff[3], support, N_NODES, 256,
        nullptr, nullptr, nullptr);
    agg_fused_kernel<256><<<AGG_GRID, 256>>>(
        support, b[3], l4, ahi, alo, l3, nullptr);                 // l4 ; planes=l4+l3

    // ---- L5 (agg-after): support = (l4+l3)@W5 ; planes = split(l5+l4+l3) -
    gemm_bf16x3_kernel<256, 128><<<dim3(GRID_M, 2), 256, 98304>>>(
        ahi, alo, whi + woff[4], wlo + woff[4], support, N_NODES, 256,
        nullptr, nullptr, nullptr);
    agg_fused_kernel<256><<<AGG_GRID, 256>>>(
        support, b[4], nullptr, ahi, alo, l4, l3);                 // planes=l5+l4+l3

    // ---- L6 (agg-after): support = (l5+l4+l3)@W6 ; out = relu(agg+b6) ----
    gemm_bf16x3_kernel<256, 128><<<dim3(GRID_M, 2), 256, 98304>>>(
        ahi, alo, whi + woff[5], wlo + woff[5], support, N_NODES, 256,
        nullptr, nullptr, nullptr);
    agg_fused_kernel<256><<<AGG_GRID, 256>>>(
        support, b[5], (float*)d_out, nullptr, nullptr, nullptr, nullptr);  // out
}

// round 14
// speedup vs baseline: 1.0425x; 1.0425x over previous
#include <cuda_runtime.h>
#include <cuda_bf16.h>
#include <cstdint>

#define N_NODES 50000
#define N_EDGES 300000
#define MAXF    256

// ---------------- scratch (device globals; no allocation allowed) ----------
__device__ float g_support[(size_t)N_NODES * MAXF];
__device__ float g_l3     [(size_t)N_NODES * MAXF];
__device__ float g_l4     [(size_t)N_NODES * MAXF];
// bf16 hi/lo planes for activations (GEMM A operand)
__device__ unsigned short g_ahi[(size_t)N_NODES * MAXF];
__device__ unsigned short g_alo[(size_t)N_NODES * MAXF];
// bf16 hi/lo planes for weights, flat-packed per layer
#define W_TOTAL 245760
__device__ unsigned short g_whi[W_TOTAL];
__device__ unsigned short g_wlo[W_TOTAL];
// CSR-by-dst edge grouping (rebuilt every call)
__device__ int    g_counts[N_NODES];
__device__ int    g_start [N_NODES];
__device__ int    g_wp    [N_NODES];
__device__ int    g_cursor;
__device__ float2 g_ebuf  [N_EDGES];    // (src as int bits, weight)

// =================== small helpers =========================================
__device__ __forceinline__ uint32_t smem_u32(const void* p) {
    uint32_t a;
    asm("{ .reg .u64 t; cvta.to.shared.u64 t, %1; cvt.u32.u64 %0, t; }"
        : "=r"(a) : "l"(p));
    return a;
}
__device__ __forceinline__ unsigned short f2bf(float x) {
    __nv_bfloat16 b = __float2bfloat16(x);
    return *(unsigned short*)&b;
}
__device__ __forceinline__ float bf2f(unsigned short u) {
    __nv_bfloat16 b = *(__nv_bfloat16*)&u;
    return __bfloat162float(b);
}
__device__ __forceinline__ void cp16(uint32_t dst, const void* src, bool valid) {
    int sz = valid ? 16 : 0;
    asm volatile("cp.async.cg.shared.global [%0], [%1], 16, %2;"
                 :: "r"(dst), "l"(src), "r"(sz));
}
__device__ __forceinline__ void ldsm4(uint32_t* r, uint32_t addr) {
    asm volatile("ldmatrix.sync.aligned.m8n8.x4.shared.b16 {%0,%1,%2,%3}, [%4];"
                 : "=r"(r[0]), "=r"(r[1]), "=r"(r[2]), "=r"(r[3]) : "r"(addr));
}
__device__ __forceinline__ void ldsm4t(uint32_t* r, uint32_t addr) {
    asm volatile("ldmatrix.sync.aligned.m8n8.x4.trans.shared.b16 {%0,%1,%2,%3}, [%4];"
                 : "=r"(r[0]), "=r"(r[1]), "=r"(r[2]), "=r"(r[3]) : "r"(addr));
}
__device__ __forceinline__ void mma_bf16(float* d, const uint32_t* a,
                                         uint32_t b0, uint32_t b1) {
    asm volatile(
        "mma.sync.aligned.m16n8k16.row.col.f32.bf16.bf16.f32 "
        "{%0,%1,%2,%3}, {%4,%5,%6,%7}, {%8,%9}, {%0,%1,%2,%3};"
        : "+f"(d[0]), "+f"(d[1]), "+f"(d[2]), "+f"(d[3])
        : "r"(a[0]), "r"(a[1]), "r"(a[2]), "r"(a[3]), "r"(b0), "r"(b1));
}

// ========== bf16x3 mma.sync GEMM: C[M,N] = A[M,K] @ W[K,N] =================
// 3-stage cp.async pipeline, ONE __syncthreads per K-tile.
template<int K, int BN>
__global__ __launch_bounds__(256, 1) void gemm_bf16x3_kernel(
    const unsigned short* __restrict__ Ahi, const unsigned short* __restrict__ Alo,
    const unsigned short* __restrict__ Whi, const unsigned short* __restrict__ Wlo,
    float* __restrict__ C, int M, int N)
{
    constexpr int NT   = K / 32;
    constexpr int BB   = 64 * BN;
    constexpr int BUFB = 16384 + 2 * BB;
    constexpr int NTN  = BN / 16;
    constexpr int NP   = NTN / 2;
    constexpr int BC   = BN / 8;

    extern __shared__ __align__(128) char smem[];
    const uint32_t sb = smem_u32(smem);

    const int tid  = threadIdx.x;
    const int lane = tid & 31;
    const int wid  = tid >> 5;
    const int m0   = blockIdx.x * 128;
    const int bn0  = blockIdx.y * BN;
    const int wm   = (wid & 3) * 32;
    const int wn   = (wid >> 2) * (BN / 2);

    float acc[2][NTN][4];
    #pragma unroll
    for (int i = 0; i < 2; i++)
        #pragma unroll
        for (int j = 0; j < NTN; j++)
            #pragma unroll
            for (int k = 0; k < 4; k++) acc[i][j][k] = 0.f;

    auto load_tile = [&](int t, int b) {
        const uint32_t base = sb + b * BUFB;
        const int kr0 = t * 32;
        #pragma unroll
        for (int i = tid; i < 512; i += 256) {
            int r = i >> 2, c = i & 3;
            int gr = m0 + r;
            uint32_t d = base + r * 64 + ((c ^ ((r >> 1) & 3)) << 4);
            size_t go = (size_t)gr * K + kr0 + c * 8;
            cp16(d,        Ahi + go, gr < M);
            cp16(d + 8192, Alo + go, gr < M);
        }
        #pragma unroll
        for (int i = tid; i < 32 * BC; i += 256) {
            int r = i / BC, c = i % BC;
            uint32_t d = base + 16384 + r * (BN * 2) + ((c ^ (r & 7)) << 4);
            size_t go = (size_t)(kr0 + r) * N + bn0 + c * 8;
            cp16(d,      Whi + go, true);
            cp16(d + BB, Wlo + go, true);
        }
        asm volatile("cp.async.commit_group;" ::: "memory");
    };

    auto compute = [&](int b) {
        const uint32_t base  = sb + b * BUFB;
        const uint32_t baseB = base + 16384;
        #pragma unroll
        for (int ks = 0; ks < 2; ks++) {
            uint32_t ah[2][4], al[2][4];
            int lrow = lane & 15;
            int lch  = 2 * ks + (lane >> 4);
            #pragma unroll
            for (int mt = 0; mt < 2; mt++) {
                int r = wm + mt * 16 + lrow;
                uint32_t addr = base + r * 64 + ((lch ^ ((r >> 1) & 3)) << 4);
                ldsm4(ah[mt], addr);
                ldsm4(al[mt], addr + 8192);
            }
            uint32_t bh[NP][4], bl[NP][4];
            int kr = ks * 16 + (lane & 15);
            #pragma unroll
            for (int np = 0; np < NP; np++) {
                int cb = (wn + np * 16 + (lane >> 4) * 8) >> 3;
                uint32_t addr = baseB + kr * (BN * 2) + ((cb ^ (kr & 7)) << 4);
                ldsm4t(bh[np], addr);
                ldsm4t(bl[np], addr + BB);
            }
            #pragma unroll
            for (int mt = 0; mt < 2; mt++)
                #pragma unroll
                for (int np = 0; np < NP; np++) {
                    mma_bf16(acc[mt][2*np],   ah[mt], bh[np][0], bh[np][1]);
                    mma_bf16(acc[mt][2*np],   ah[mt], bl[np][0], bl[np][1]);
                    mma_bf16(acc[mt][2*np],   al[mt], bh[np][0], bh[np][1]);
                    mma_bf16(acc[mt][2*np+1], ah[mt], bh[np][2], bh[np][3]);
                    mma_bf16(acc[mt][2*np+1], ah[mt], bl[np][2], bl[np][3]);
                    mma_bf16(acc[mt][2*np+1], al[mt], bh[np][2], bh[np][3]);
                }
        }
    };

    // 3-stage pipeline prologue
    load_tile(0, 0);
    if (NT > 1) load_tile(1, 1);

    #pragma unroll 1
    for (int t = 0; t < NT; t++) {
        if (t + 1 < NT) {
            asm volatile("cp.async.wait_group 1;" ::: "memory");
        } else {
            asm volatile("cp.async.wait_group 0;" ::: "memory");
        }
        __syncthreads();
        compute(t % 3);
        if (t + 2 < NT) load_tile(t + 2, (t + 2) % 3);
    }

    #pragma unroll
    for (int mt = 0; mt < 2; mt++)
        #pragma unroll
        for (int nt = 0; nt < NTN; nt++) {
            int row = m0 + wm + mt * 16 + (lane >> 2);
            int col = bn0 + wn + nt * 8 + (lane & 3) * 2;
            if (row < M)
                *(float2*)&C[(size_t)row * N + col] =
                    make_float2(acc[mt][nt][0], acc[mt][nt][1]);
            if (row + 8 < M)
                *(float2*)&C[(size_t)(row + 8) * N + col] =
                    make_float2(acc[mt][nt][2], acc[mt][nt][3]);
        }
}

// ------- batched prologue: CSR-zero + weight splits + x split, ONE launch --
struct SplitArgs {
    const float4* w[6];     // weight tensors
    const float4* x;        // input features
};
#define ZERO_BLOCKS 196     // ceil(50000/256) -> csr counts zero + cursor
#define WSEG_BLOCKS 240     // 61440 float4s of weights / 256
#define XSEG_N4     1600000 // 50000*128/4

__global__ void prologue_kernel(SplitArgs a,
                                ushort4* __restrict__ whi4, ushort4* __restrict__ wlo4,
                                ushort4* __restrict__ ahi4, ushort4* __restrict__ alo4)
{
    int bid = blockIdx.x;
    if (bid < ZERO_BLOCKS) {
        int i = bid * 256 + threadIdx.x;
        if (i < N_NODES) g_counts[i] = 0;
        if (i == 0) g_cursor = 0;
        return;
    }
    bid -= ZERO_BLOCKS;
    float4 v;
    ushort4* dh;
    ushort4* dl;
    int oi;
    if (bid < WSEG_BLOCKS) {
        int i = bid * 256 + threadIdx.x;          // [0, 61440)
        int seg = (i >= 2048) + (i >= 4096) + (i >= 12288) + (i >= 28672) + (i >= 45056);
        static const int off[6] = {0, 2048, 4096, 12288, 28672, 45056};
        v = __ldg(&a.w[seg][i - off[seg]]);
        dh = whi4; dl = wlo4; oi = i;
    } else {
        int i = (bid - WSEG_BLOCKS) * 256 + threadIdx.x;
        if (i >= XSEG_N4) return;
        v = __ldg(&a.x[i]);
        dh = ahi4; dl = alo4; oi = i;
    }
    ushort4 h, l;
    h.x = f2bf(v.x); l.x = f2bf(v.x - bf2f(h.x));
    h.y = f2bf(v.y); l.y = f2bf(v.y - bf2f(h.y));
    h.z = f2bf(v.z); l.z = f2bf(v.z - bf2f(h.z));
    h.w = f2bf(v.w); l.w = f2bf(v.w - bf2f(h.w));
    dh[oi] = h; dl[oi] = l;
}

// ---------------- CSR build (3 tiny kernels after prologue) ----------------
__global__ void csr_hist_kernel(const int* __restrict__ dst)
{
    int e = blockIdx.x * blockDim.x + threadIdx.x;
    if (e < N_EDGES) atomicAdd(&g_counts[dst[e]], 1);
}
__global__ void csr_alloc_kernel()
{
    int i = blockIdx.x * blockDim.x + threadIdx.x;
    if (i < N_NODES) {
        int s = atomicAdd(&g_cursor, g_counts[i]);
        g_start[i] = s;
        g_wp[i]    = s;
    }
}
__global__ void csr_scatter_kernel(const int* __restrict__ src,
                                   const int* __restrict__ dst,
                                   const float* __restrict__ w)
{
    int e = blockIdx.x * blockDim.x + threadIdx.x;
    if (e >= N_EDGES) return;
    int pos = atomicAdd(&g_wp[dst[e]], 1);
    g_ebuf[pos] = make_float2(__int_as_float(src[e]), w[e]);
}

// ====== fused aggregation: warp per node, 2-edge MLP (round-6 winner) ======
// out_row = relu( sum_e w_e * support[src_e] + bias )
// optional: out_f32 <- out_row ; planes <- split(out_row + add1 + add2)
template<int N>
__global__ __launch_bounds__(256) void agg_fused_kernel(
    const float* __restrict__ support,
    const float* __restrict__ bias,
    float* __restrict__ out_f32,
    ushort* __restrict__ hi, ushort* __restrict__ lo,
    const float* __restrict__ add1,
    const float* __restrict__ add2)
{
    int warp = (blockIdx.x * blockDim.x + threadIdx.x) >> 5;
    if (warp >= N_NODES) return;
    int lane = threadIdx.x & 31;
    int s   = __ldg(&g_start[warp]);
    int end = s + __ldg(&g_counts[warp]);

    constexpr int FPN = N / 32;    // 2, 4, or 8 floats per lane
    float acc[FPN];
    #pragma unroll
    for (int j = 0; j < FPN; j++) acc[j] = 0.f;

    auto gather1 = [&](float2 p) {
        int   src = __float_as_int(p.x);
        float w   = p.y;
        const float* row = support + (size_t)src * N;
        if (FPN == 2) {
            float2 v = __ldg((const float2*)&row[lane * 2]);
            acc[0] += v.x * w; acc[1] += v.y * w;
        } else if (FPN == 4) {
            float4 v = __ldg((const float4*)&row[lane * 4]);
            acc[0] += v.x * w; acc[1] += v.y * w;
            acc[2] += v.z * w; acc[3] += v.w * w;
        } else {
            float4 v0 = __ldg((const float4*)&row[lane * 4]);
            float4 v1 = __ldg((const float4*)&row[128 + lane * 4]);
            acc[0] += v0.x * w; acc[1] += v0.y * w;
            acc[2] += v0.z * w; acc[3] += v0.w * w;
            acc[4] += v1.x * w; acc[5] += v1.y * w;
            acc[6] += v1.z * w; acc[7] += v1.w * w;
        }
    };

    int e = s;
    #pragma unroll 1
    for (; e + 1 < end; e += 2) {
        // both edge records first, then two independent row gathers -> MLP 2
        float2 p0 = __ldg(&g_ebuf[e]);
        float2 p1 = __ldg(&g_ebuf[e + 1]);
        gather1(p0);
        gather1(p1);
    }
    if (e < end) gather1(__ldg(&g_ebuf[e]));

    int col0 = (FPN == 2) ? lane * 2 : lane * 4;
    size_t rowo = (size_t)warp * N;

    float r[FPN];
    #pragma unroll
    for (int j = 0; j < FPN; j++) {
        int col = (j < 4) ? col0 + j : 128 + col0 + (j - 4);
        r[j] = fmaxf(acc[j] + __ldg(&bias[col]), 0.f);
    }
    if (out_f32) {
        if (FPN == 2)
            *(float2*)&out_f32[rowo + col0] = make_float2(r[0], r[1]);
        else {
            *(float4*)&out_f32[rowo + col0] = make_float4(r[0], r[1], r[2], r[3]);
            if (FPN == 8)
                *(float4*)&out_f32[rowo + 128 + col0] = make_float4(r[4], r[5], r[6], r[7]);
        }
    }
    if (hi) {
        float sv[FPN];
        #pragma unroll
        for (int j = 0; j < FPN; j++) sv[j] = r[j];
        if (add1) {
            #pragma unroll
            for (int j = 0; j < FPN; j++) {
                int col = (j < 4) ? col0 + j : 128 + col0 + (j - 4);
                sv[j] += __ldg(&add1[rowo + col]);
            }
        }
        if (add2) {
            #pragma unroll
            for (int j = 0; j < FPN; j++) {
                int col = (j < 4) ? col0 + j : 128 + col0 + (j - 4);
                sv[j] += __ldg(&add2[rowo + col]);
            }
        }
        unsigned short hv[FPN], lv[FPN];
        #pragma unroll
        for (int j = 0; j < FPN; j++) {
            hv[j] = f2bf(sv[j]);
            lv[j] = f2bf(sv[j] - bf2f(hv[j]));
        }
        if (FPN == 2) {
            *(ushort2*)&hi[rowo + col0] = make_ushort2(hv[0], hv[1]);
            *(ushort2*)&lo[rowo + col0] = make_ushort2(lv[0], lv[1]);
        } else {
            *(ushort4*)&hi[rowo + col0] = make_ushort4(hv[0], hv[1], hv[2], hv[3]);
            *(ushort4*)&lo[rowo + col0] = make_ushort4(lv[0], lv[1], lv[2], lv[3]);
            if (FPN == 8) {
                *(ushort4*)&hi[rowo + 128 + col0] = make_ushort4(hv[4], hv[5], hv[6], hv[7]);
                *(ushort4*)&lo[rowo + 128 + col0] = make_ushort4(lv[4], lv[5], lv[6], lv[7]);
            }
        }
    }
}

// ---------------------------------------------------------------------------
extern "C" void kernel_launch(void* const* d_in, const int* in_sizes, int n_in,
                              void* d_out, int out_size)
{
    const float* x    = (const float*)d_in[0];
    const int*   esrc = (const int*)  d_in[1];
    const int*   edst = (const int*)  d_in[2];
    const float* ew   = (const float*)d_in[3];
    const float* W[6];
    const float* b[6];
    for (int i = 0; i < 6; i++) {
        W[i] = (const float*)d_in[4 + 2 * i];
        b[i] = (const float*)d_in[5 + 2 * i];
    }

    float *support, *l3, *l4;
    unsigned short *ahi, *alo, *whi, *wlo;
    cudaGetSymbolAddress((void**)&support, g_support);
    cudaGetSymbolAddress((void**)&l3,      g_l3);
    cudaGetSymbolAddress((void**)&l4,      g_l4);
    cudaGetSymbolAddress((void**)&ahi,     g_ahi);
    cudaGetSymbolAddress((void**)&alo,     g_alo);
    cudaGetSymbolAddress((void**)&whi,     g_whi);
    cudaGetSymbolAddress((void**)&wlo,     g_wlo);

    static const int woff[6] = {0, 8192, 16384, 49152, 114688, 180224};

    // 3-stage pipeline smem: BUFB*3; BN=64: 24576*3, BN=128: 32768*3
    cudaFuncSetAttribute(gemm_bf16x3_kernel<128, 64>,
        cudaFuncAttributeMaxDynamicSharedMemorySize, 73728);
    cudaFuncSetAttribute(gemm_bf16x3_kernel<64, 128>,
        cudaFuncAttributeMaxDynamicSharedMemorySize, 98304);
    cudaFuncSetAttribute(gemm_bf16x3_kernel<128, 128>,
        cudaFuncAttributeMaxDynamicSharedMemorySize, 98304);
    cudaFuncSetAttribute(gemm_bf16x3_kernel<256, 128>,
        cudaFuncAttributeMaxDynamicSharedMemorySize, 98304);

    // ---- prologue: csr-zero + all splits in ONE launch -------------------
    {
        SplitArgs a;
        for (int i = 0; i < 6; i++) a.w[i] = (const float4*)W[i];
        a.x = (const float4*)x;
        int grid = ZERO_BLOCKS + WSEG_BLOCKS + (XSEG_N4 + 255) / 256;
        prologue_kernel<<<grid, 256>>>(a, (ushort4*)whi, (ushort4*)wlo,
                                       (ushort4*)ahi, (ushort4*)alo);
    }
    // ---- CSR-by-dst build ------------------------------------------------
    csr_hist_kernel<<<(N_EDGES + 255) / 256, 256>>>(edst);
    csr_alloc_kernel<<<(N_NODES + 255) / 256, 256>>>();
    csr_scatter_kernel<<<(N_EDGES + 255) / 256, 256>>>(esrc, edst, ew);

    const int GRID_M   = (N_NODES + 127) / 128;            // 391
    const int AGG_GRID = (N_NODES * 32 + 255) / 256;       // warp per node

    // L1: x(128) -> 64
    gemm_bf16x3_kernel<128, 64><<<dim3(GRID_M, 1), 256, 73728>>>(
        ahi, alo, whi + woff[0], wlo + woff[0], support, N_NODES, 64);
    agg_fused_kernel<64><<<AGG_GRID, 256>>>(
        support, b[0], nullptr, ahi, alo, nullptr, nullptr);       // planes = l1
    // L2: 64 -> 128
    gemm_bf16x3_kernel<64, 128><<<dim3(GRID_M, 1), 256, 98304>>>(
        ahi, alo, whi + woff[1], wlo + woff[1], support, N_NODES, 128);
    agg_fused_kernel<128><<<AGG_GRID, 256>>>(
        support, b[1], nullptr, ahi, alo, nullptr, nullptr);       // planes = l2
    // L3: 128 -> 256
    gemm_bf16x3_kernel<128, 128><<<dim3(GRID_M, 2), 256, 98304>>>(
        ahi, alo, whi + woff[2], wlo + woff[2], support, N_NODES, 256);
    agg_fused_kernel<256><<<AGG_GRID, 256>>>(
        support, b[2], l3, ahi, alo, nullptr, nullptr);            // l3 ; planes = l3
    // L4: l3 -> 256
    gemm_bf16x3_kernel<256, 128><<<dim3(GRID_M, 2), 256, 98304>>>(
        ahi, alo, whi + woff[3], wlo + woff[3], support, N_NODES, 256);
    agg_fused_kernel<256><<<AGG_GRID, 256>>>(
        support, b[3], l4, ahi, alo, l3, nullptr);                 // l4 ; planes = l4+l3
    // L5: (l4+l3) -> 256
    gemm_bf16x3_kernel<256, 128><<<dim3(GRID_M, 2), 256, 98304>>>(
        ahi, alo, whi + woff[4], wlo + woff[4], support, N_NODES, 256);
    agg_fused_kernel<256><<<AGG_GRID, 256>>>(
        support, b[4], nullptr, ahi, alo, l4, l3);                 // planes = l5+l4+l3
    // L6: (l5+l4+l3) -> 256
    gemm_bf16x3_kernel<256, 128><<<dim3(GRID_M, 2), 256, 98304>>>(
        ahi, alo, whi + woff[5], wlo + woff[5], support, N_NODES, 256);
    agg_fused_kernel<256><<<AGG_GRID, 256>>>(
        support, b[5], (float*)d_out, nullptr, nullptr, nullptr, nullptr);  // out
}

// round 16
// speedup vs baseline: 1.0530x; 1.0100x over previous
#include <cuda_runtime.h>
#include <cuda_bf16.h>
#include <cstdint>

#define N_NODES 50000
#define N_EDGES 300000
#define MAXF    256

// ---------------- scratch (device globals; no allocation allowed) ----------
__device__ float g_support[(size_t)N_NODES * MAXF];
__device__ float g_l3     [(size_t)N_NODES * MAXF];
__device__ float g_l4     [(size_t)N_NODES * MAXF];
// bf16 hi/lo planes for activations (GEMM A operand)
__device__ unsigned short g_ahi[(size_t)N_NODES * MAXF];
__device__ unsigned short g_alo[(size_t)N_NODES * MAXF];
// bf16 hi/lo planes for weights, flat-packed per layer
#define W_TOTAL 245760
__device__ unsigned short g_whi[W_TOTAL];
__device__ unsigned short g_wlo[W_TOTAL];
// CSR-by-dst edge grouping (rebuilt every call)
__device__ int    g_counts[N_NODES];
__device__ int    g_start [N_NODES];
__device__ int    g_wp    [N_NODES];
__device__ int    g_cursor;
__device__ float2 g_ebuf  [N_EDGES];    // (src as int bits, weight)

// =================== small helpers =========================================
__device__ __forceinline__ uint32_t smem_u32(const void* p) {
    uint32_t a;
    asm("{ .reg .u64 t; cvta.to.shared.u64 t, %1; cvt.u32.u64 %0, t; }"
        : "=r"(a) : "l"(p));
    return a;
}
__device__ __forceinline__ unsigned short f2bf(float x) {
    __nv_bfloat16 b = __float2bfloat16(x);
    return *(unsigned short*)&b;
}
__device__ __forceinline__ float bf2f(unsigned short u) {
    __nv_bfloat16 b = *(__nv_bfloat16*)&u;
    return __bfloat162float(b);
}
__device__ __forceinline__ void cp16(uint32_t dst, const void* src, bool valid) {
    int sz = valid ? 16 : 0;
    asm volatile("cp.async.cg.shared.global [%0], [%1], 16, %2;"
                 :: "r"(dst), "l"(src), "r"(sz));
}
__device__ __forceinline__ void ldsm4(uint32_t* r, uint32_t addr) {
    asm volatile("ldmatrix.sync.aligned.m8n8.x4.shared.b16 {%0,%1,%2,%3}, [%4];"
                 : "=r"(r[0]), "=r"(r[1]), "=r"(r[2]), "=r"(r[3]) : "r"(addr));
}
__device__ __forceinline__ void ldsm4t(uint32_t* r, uint32_t addr) {
    asm volatile("ldmatrix.sync.aligned.m8n8.x4.trans.shared.b16 {%0,%1,%2,%3}, [%4];"
                 : "=r"(r[0]), "=r"(r[1]), "=r"(r[2]), "=r"(r[3]) : "r"(addr));
}
__device__ __forceinline__ void mma_bf16(float* d, const uint32_t* a,
                                         uint32_t b0, uint32_t b1) {
    asm volatile(
        "mma.sync.aligned.m16n8k16.row.col.f32.bf16.bf16.f32 "
        "{%0,%1,%2,%3}, {%4,%5,%6,%7}, {%8,%9}, {%0,%1,%2,%3};"
        : "+f"(d[0]), "+f"(d[1]), "+f"(d[2]), "+f"(d[3])
        : "r"(a[0]), "r"(a[1]), "r"(a[2]), "r"(a[3]), "r"(b0), "r"(b1));
}

// ========== bf16x3 mma.sync GEMM: C[M,N] = A[M,K] @ W[K,N] =================
// 3-stage cp.async pipeline, ONE __syncthreads per K-tile.
// MINB: min blocks/SM for __launch_bounds (2 for the small BN=64 kernel).
template<int K, int BN, int MINB>
__global__ __launch_bounds__(256, MINB) void gemm_bf16x3_kernel(
    const unsigned short* __restrict__ Ahi, const unsigned short* __restrict__ Alo,
    const unsigned short* __restrict__ Whi, const unsigned short* __restrict__ Wlo,
    float* __restrict__ C, int M, int N)
{
    constexpr int NT   = K / 32;
    constexpr int BB   = 64 * BN;
    constexpr int BUFB = 16384 + 2 * BB;
    constexpr int NTN  = BN / 16;
    constexpr int NP   = NTN / 2;
    constexpr int BC   = BN / 8;

    extern __shared__ __align__(128) char smem[];
    const uint32_t sb = smem_u32(smem);

    const int tid  = threadIdx.x;
    const int lane = tid & 31;
    const int wid  = tid >> 5;
    const int m0   = blockIdx.x * 128;
    const int bn0  = blockIdx.y * BN;
    const int wm   = (wid & 3) * 32;
    const int wn   = (wid >> 2) * (BN / 2);

    float acc[2][NTN][4];
    #pragma unroll
    for (int i = 0; i < 2; i++)
        #pragma unroll
        for (int j = 0; j < NTN; j++)
            #pragma unroll
            for (int k = 0; k < 4; k++) acc[i][j][k] = 0.f;

    auto load_tile = [&](int t, int b) {
        const uint32_t base = sb + b * BUFB;
        const int kr0 = t * 32;
        #pragma unroll
        for (int i = tid; i < 512; i += 256) {
            int r = i >> 2, c = i & 3;
            int gr = m0 + r;
            uint32_t d = base + r * 64 + ((c ^ ((r >> 1) & 3)) << 4);
            size_t go = (size_t)gr * K + kr0 + c * 8;
            cp16(d,        Ahi + go, gr < M);
            cp16(d + 8192, Alo + go, gr < M);
        }
        #pragma unroll
        for (int i = tid; i < 32 * BC; i += 256) {
            int r = i / BC, c = i % BC;
            uint32_t d = base + 16384 + r * (BN * 2) + ((c ^ (r & 7)) << 4);
            size_t go = (size_t)(kr0 + r) * N + bn0 + c * 8;
            cp16(d,      Whi + go, true);
            cp16(d + BB, Wlo + go, true);
        }
        asm volatile("cp.async.commit_group;" ::: "memory");
    };

    auto compute = [&](int b) {
        const uint32_t base  = sb + b * BUFB;
        const uint32_t baseB = base + 16384;
        #pragma unroll
        for (int ks = 0; ks < 2; ks++) {
            uint32_t ah[2][4], al[2][4];
            int lrow = lane & 15;
            int lch  = 2 * ks + (lane >> 4);
            #pragma unroll
            for (int mt = 0; mt < 2; mt++) {
                int r = wm + mt * 16 + lrow;
                uint32_t addr = base + r * 64 + ((lch ^ ((r >> 1) & 3)) << 4);
                ldsm4(ah[mt], addr);
                ldsm4(al[mt], addr + 8192);
            }
            uint32_t bh[NP][4], bl[NP][4];
            int kr = ks * 16 + (lane & 15);
            #pragma unroll
            for (int np = 0; np < NP; np++) {
                int cb = (wn + np * 16 + (lane >> 4) * 8) >> 3;
                uint32_t addr = baseB + kr * (BN * 2) + ((cb ^ (kr & 7)) << 4);
                ldsm4t(bh[np], addr);
                ldsm4t(bl[np], addr + BB);
            }
            #pragma unroll
            for (int mt = 0; mt < 2; mt++)
                #pragma unroll
                for (int np = 0; np < NP; np++) {
                    mma_bf16(acc[mt][2*np],   ah[mt], bh[np][0], bh[np][1]);
                    mma_bf16(acc[mt][2*np],   ah[mt], bl[np][0], bl[np][1]);
                    mma_bf16(acc[mt][2*np],   al[mt], bh[np][0], bh[np][1]);
                    mma_bf16(acc[mt][2*np+1], ah[mt], bh[np][2], bh[np][3]);
                    mma_bf16(acc[mt][2*np+1], ah[mt], bl[np][2], bl[np][3]);
                    mma_bf16(acc[mt][2*np+1], al[mt], bh[np][2], bh[np][3]);
                }
        }
    };

    // 3-stage pipeline prologue
    load_tile(0, 0);
    if (NT > 1) load_tile(1, 1);

    #pragma unroll 1
    for (int t = 0; t < NT; t++) {
        if (t + 1 < NT) {
            asm volatile("cp.async.wait_group 1;" ::: "memory");
        } else {
            asm volatile("cp.async.wait_group 0;" ::: "memory");
        }
        __syncthreads();
        compute(t % 3);
        if (t + 2 < NT) load_tile(t + 2, (t + 2) % 3);
    }

    #pragma unroll
    for (int mt = 0; mt < 2; mt++)
        #pragma unroll
        for (int nt = 0; nt < NTN; nt++) {
            int row = m0 + wm + mt * 16 + (lane >> 2);
            int col = bn0 + wn + nt * 8 + (lane & 3) * 2;
            if (row < M)
                *(float2*)&C[(size_t)row * N + col] =
                    make_float2(acc[mt][nt][0], acc[mt][nt][1]);
            if (row + 8 < M)
                *(float2*)&C[(size_t)(row + 8) * N + col] =
                    make_float2(acc[mt][nt][2], acc[mt][nt][3]);
        }
}

// ------- batched prologue: CSR-zero + weight splits + x split, ONE launch --
struct SplitArgs {
    const float4* w[6];     // weight tensors
    const float4* x;        // input features
};
#define ZERO_BLOCKS 196     // ceil(50000/256) -> csr counts zero + cursor
#define WSEG_BLOCKS 240     // 61440 float4s of weights / 256
#define XSEG_N4     1600000 // 50000*128/4

__global__ void prologue_kernel(SplitArgs a,
                                ushort4* __restrict__ whi4, ushort4* __restrict__ wlo4,
                                ushort4* __restrict__ ahi4, ushort4* __restrict__ alo4)
{
    int bid = blockIdx.x;
    if (bid < ZERO_BLOCKS) {
        int i = bid * 256 + threadIdx.x;
        if (i < N_NODES) g_counts[i] = 0;
        if (i == 0) g_cursor = 0;
        return;
    }
    bid -= ZERO_BLOCKS;
    float4 v;
    ushort4* dh;
    ushort4* dl;
    int oi;
    if (bid < WSEG_BLOCKS) {
        int i = bid * 256 + threadIdx.x;          // [0, 61440)
        int seg = (i >= 2048) + (i >= 4096) + (i >= 12288) + (i >= 28672) + (i >= 45056);
        static const int off[6] = {0, 2048, 4096, 12288, 28672, 45056};
        v = __ldg(&a.w[seg][i - off[seg]]);
        dh = whi4; dl = wlo4; oi = i;
    } else {
        int i = (bid - WSEG_BLOCKS) * 256 + threadIdx.x;
        if (i >= XSEG_N4) return;
        v = __ldg(&a.x[i]);
        dh = ahi4; dl = alo4; oi = i;
    }
    ushort4 h, l;
    h.x = f2bf(v.x); l.x = f2bf(v.x - bf2f(h.x));
    h.y = f2bf(v.y); l.y = f2bf(v.y - bf2f(h.y));
    h.z = f2bf(v.z); l.z = f2bf(v.z - bf2f(h.z));
    h.w = f2bf(v.w); l.w = f2bf(v.w - bf2f(h.w));
    dh[oi] = h; dl[oi] = l;
}

// ---------------- CSR build (3 tiny kernels after prologue) ----------------
__global__ void csr_hist_kernel(const int* __restrict__ dst)
{
    int e = blockIdx.x * blockDim.x + threadIdx.x;
    if (e < N_EDGES) atomicAdd(&g_counts[dst[e]], 1);
}
__global__ void csr_alloc_kernel()
{
    int i = blockIdx.x * blockDim.x + threadIdx.x;
    if (i < N_NODES) {
        int s = atomicAdd(&g_cursor, g_counts[i]);
        g_start[i] = s;
        g_wp[i]    = s;
    }
}
__global__ void csr_scatter_kernel(const int* __restrict__ src,
                                   const int* __restrict__ dst,
                                   const float* __restrict__ w)
{
    int e = blockIdx.x * blockDim.x + threadIdx.x;
    if (e >= N_EDGES) return;
    int pos = atomicAdd(&g_wp[dst[e]], 1);
    g_ebuf[pos] = make_float2(__int_as_float(src[e]), w[e]);
}

// ====== fused aggregation: warp per node, 2-edge MLP (round-6 winner) ======
// out_row = relu( sum_e w_e * support[src_e] + bias )
// optional: out_f32 <- out_row ; planes <- split(out_row + add1 + add2)
template<int N>
__global__ __launch_bounds__(256) void agg_fused_kernel(
    const float* __restrict__ support,
    const float* __restrict__ bias,
    float* __restrict__ out_f32,
    ushort* __restrict__ hi, ushort* __restrict__ lo,
    const float* __restrict__ add1,
    const float* __restrict__ add2)
{
    int warp = (blockIdx.x * blockDim.x + threadIdx.x) >> 5;
    if (warp >= N_NODES) return;
    int lane = threadIdx.x & 31;
    int s   = __ldg(&g_start[warp]);
    int end = s + __ldg(&g_counts[warp]);

    constexpr int FPN = N / 32;    // 2, 4, or 8 floats per lane
    float acc[FPN];
    #pragma unroll
    for (int j = 0; j < FPN; j++) acc[j] = 0.f;

    auto gather1 = [&](float2 p) {
        int   src = __float_as_int(p.x);
        float w   = p.y;
        const float* row = support + (size_t)src * N;
        if (FPN == 2) {
            float2 v = __ldg((const float2*)&row[lane * 2]);
            acc[0] += v.x * w; acc[1] += v.y * w;
        } else if (FPN == 4) {
            float4 v = __ldg((const float4*)&row[lane * 4]);
            acc[0] += v.x * w; acc[1] += v.y * w;
            acc[2] += v.z * w; acc[3] += v.w * w;
        } else {
            float4 v0 = __ldg((const float4*)&row[lane * 4]);
            float4 v1 = __ldg((const float4*)&row[128 + lane * 4]);
            acc[0] += v0.x * w; acc[1] += v0.y * w;
            acc[2] += v0.z * w; acc[3] += v0.w * w;
            acc[4] += v1.x * w; acc[5] += v1.y * w;
            acc[6] += v1.z * w; acc[7] += v1.w * w;
        }
    };

    int e = s;
    #pragma unroll 1
    for (; e + 1 < end; e += 2) {
        // both edge records first, then two independent row gathers -> MLP 2
        float2 p0 = __ldg(&g_ebuf[e]);
        float2 p1 = __ldg(&g_ebuf[e + 1]);
        gather1(p0);
        gather1(p1);
    }
    if (e < end) gather1(__ldg(&g_ebuf[e]));

    int col0 = (FPN == 2) ? lane * 2 : lane * 4;
    size_t rowo = (size_t)warp * N;

    float r[FPN];
    #pragma unroll
    for (int j = 0; j < FPN; j++) {
        int col = (j < 4) ? col0 + j : 128 + col0 + (j - 4);
        r[j] = fmaxf(acc[j] + __ldg(&bias[col]), 0.f);
    }
    if (out_f32) {
        if (FPN == 2)
            *(float2*)&out_f32[rowo + col0] = make_float2(r[0], r[1]);
        else {
            *(float4*)&out_f32[rowo + col0] = make_float4(r[0], r[1], r[2], r[3]);
            if (FPN == 8)
                *(float4*)&out_f32[rowo + 128 + col0] = make_float4(r[4], r[5], r[6], r[7]);
        }
    }
    if (hi) {
        float sv[FPN];
        #pragma unroll
        for (int j = 0; j < FPN; j++) sv[j] = r[j];
        if (add1) {
            #pragma unroll
            for (int j = 0; j < FPN; j++) {
                int col = (j < 4) ? col0 + j : 128 + col0 + (j - 4);
                sv[j] += __ldg(&add1[rowo + col]);
            }
        }
        if (add2) {
            #pragma unroll
            for (int j = 0; j < FPN; j++) {
                int col = (j < 4) ? col0 + j : 128 + col0 + (j - 4);
                sv[j] += __ldg(&add2[rowo + col]);
            }
        }
        unsigned short hv[FPN], lv[FPN];
        #pragma unroll
        for (int j = 0; j < FPN; j++) {
            hv[j] = f2bf(sv[j]);
            lv[j] = f2bf(sv[j] - bf2f(hv[j]));
        }
        if (FPN == 2) {
            *(ushort2*)&hi[rowo + col0] = make_ushort2(hv[0], hv[1]);
            *(ushort2*)&lo[rowo + col0] = make_ushort2(lv[0], lv[1]);
        } else {
            *(ushort4*)&hi[rowo + col0] = make_ushort4(hv[0], hv[1], hv[2], hv[3]);
            *(ushort4*)&lo[rowo + col0] = make_ushort4(lv[0], lv[1], lv[2], lv[3]);
            if (FPN == 8) {
                *(ushort4*)&hi[rowo + 128 + col0] = make_ushort4(hv[4], hv[5], hv[6], hv[7]);
                *(ushort4*)&lo[rowo + 128 + col0] = make_ushort4(lv[4], lv[5], lv[6], lv[7]);
            }
        }
    }
}

// ---------------------------------------------------------------------------
extern "C" void kernel_launch(void* const* d_in, const int* in_sizes, int n_in,
                              void* d_out, int out_size)
{
    const float* x    = (const float*)d_in[0];
    const int*   esrc = (const int*)  d_in[1];
    const int*   edst = (const int*)  d_in[2];
    const float* ew   = (const float*)d_in[3];
    const float* W[6];
    const float* b[6];
    for (int i = 0; i < 6; i++) {
        W[i] = (const float*)d_in[4 + 2 * i];
        b[i] = (const float*)d_in[5 + 2 * i];
    }

    float *support, *l3, *l4;
    unsigned short *ahi, *alo, *whi, *wlo;
    cudaGetSymbolAddress((void**)&support, g_support);
    cudaGetSymbolAddress((void**)&l3,      g_l3);
    cudaGetSymbolAddress((void**)&l4,      g_l4);
    cudaGetSymbolAddress((void**)&ahi,     g_ahi);
    cudaGetSymbolAddress((void**)&alo,     g_alo);
    cudaGetSymbolAddress((void**)&whi,     g_whi);
    cudaGetSymbolAddress((void**)&wlo,     g_wlo);

    static const int woff[6] = {0, 8192, 16384, 49152, 114688, 180224};

    // one-time side stream + events (identical work on every call; capture
    // picks up the cross-stream dependency via the fork/join events)
    static cudaStream_t s_side = nullptr;
    static cudaEvent_t  s_fork = nullptr, s_join = nullptr;
    if (s_side == nullptr) {
        cudaStreamCreateWithFlags(&s_side, cudaStreamNonBlocking);
        cudaEventCreateWithFlags(&s_fork, cudaEventDisableTiming);
        cudaEventCreateWithFlags(&s_join, cudaEventDisableTiming);
    }

    // 3-stage pipeline smem: BUFB*3; BN=64: 24576*3, BN=128: 32768*3
    cudaFuncSetAttribute(gemm_bf16x3_kernel<128, 64, 2>,
        cudaFuncAttributeMaxDynamicSharedMemorySize, 73728);
    cudaFuncSetAttribute(gemm_bf16x3_kernel<64, 128, 1>,
        cudaFuncAttributeMaxDynamicSharedMemorySize, 98304);
    cudaFuncSetAttribute(gemm_bf16x3_kernel<128, 128, 1>,
        cudaFuncAttributeMaxDynamicSharedMemorySize, 98304);
    cudaFuncSetAttribute(gemm_bf16x3_kernel<256, 128, 1>,
        cudaFuncAttributeMaxDynamicSharedMemorySize, 98304);

    // ---- prologue: csr-zero + all splits in ONE launch -------------------
    {
        SplitArgs a;
        for (int i = 0; i < 6; i++) a.w[i] = (const float4*)W[i];
        a.x = (const float4*)x;
        int grid = ZERO_BLOCKS + WSEG_BLOCKS + (XSEG_N4 + 255) / 256;
        prologue_kernel<<<grid, 256>>>(a, (ushort4*)whi, (ushort4*)wlo,
                                       (ushort4*)ahi, (ushort4*)alo);
    }

    const int GRID_M   = (N_NODES + 127) / 128;            // 391
    const int AGG_GRID = (N_NODES * 32 + 255) / 256;       // warp per node

    // ---- fork: CSR chain on side stream, L1 GEMM on main stream ----------
    cudaEventRecord(s_fork, 0);
    cudaStreamWaitEvent(s_side, s_fork, 0);
    csr_hist_kernel<<<(N_EDGES + 255) / 256, 256, 0, s_side>>>(edst);
    csr_alloc_kernel<<<(N_NODES + 255) / 256, 256, 0, s_side>>>();
    csr_scatter_kernel<<<(N_EDGES + 255) / 256, 256, 0, s_side>>>(esrc, edst, ew);
    cudaEventRecord(s_join, s_side);

    // L1 GEMM (independent of CSR): support = x@W1
    gemm_bf16x3_kernel<128, 64, 2><<<dim3(GRID_M, 1), 256, 73728>>>(
        ahi, alo, whi + woff[0], wlo + woff[0], support, N_NODES, 64);

    // join: agg needs both CSR and support
    cudaStreamWaitEvent(0, s_join, 0);

    agg_fused_kernel<64><<<AGG_GRID, 256>>>(
        support, b[0], nullptr, ahi, alo, nullptr, nullptr);       // planes = l1
    // L2: 64 -> 128
    gemm_bf16x3_kernel<64, 128, 1><<<dim3(GRID_M, 1), 256, 98304>>>(
        ahi, alo, whi + woff[1], wlo + woff[1], support, N_NODES, 128);
    agg_fused_kernel<128><<<AGG_GRID, 256>>>(
        support, b[1], nullptr, ahi, alo, nullptr, nullptr);       // planes = l2
    // L3: 128 -> 256
    gemm_bf16x3_kernel<128, 128, 1><<<dim3(GRID_M, 2), 256, 98304>>>(
        ahi, alo, whi + woff[2], wlo + woff[2], support, N_NODES, 256);
    agg_fused_kernel<256><<<AGG_GRID, 256>>>(
        support, b[2], l3, ahi, alo, nullptr, nullptr);            // l3 ; planes = l3
    // L4: l3 -> 256
    gemm_bf16x3_kernel<256, 128, 1><<<dim3(GRID_M, 2), 256, 98304>>>(
        ahi, alo, whi + woff[3], wlo + woff[3], support, N_NODES, 256);
    agg_fused_kernel<256><<<AGG_GRID, 256>>>(
        support, b[3], l4, ahi, alo, l3, nullptr);                 // l4 ; planes = l4+l3
    // L5: (l4+l3) -> 256
    gemm_bf16x3_kernel<256, 128, 1><<<dim3(GRID_M, 2), 256, 98304>>>(
        ahi, alo, whi + woff[4], wlo + woff[4], support, N_NODES, 256);
    agg_fused_kernel<256><<<AGG_GRID, 256>>>(
        support, b[4], nullptr, ahi, alo, l4, l3);                 // planes = l5+l4+l3
    // L6: (l5+l4+l3) -> 256
    gemm_bf16x3_kernel<256, 128, 1><<<dim3(GRID_M, 2), 256, 98304>>>(
        ahi, alo, whi + woff[5], wlo + woff[5], support, N_NODES, 256);
    agg_fused_kernel<256><<<AGG_GRID, 256>>>(
        support, b[5], (float*)d_out, nullptr, nullptr, nullptr, nullptr);  // out
}